// round 5
// baseline (speedup 1.0000x reference)
#include <cuda_runtime.h>
#include <cuda_bf16.h>
#include <cstdint>

// ============================================================================
// B=4096 features [B,256], K=8192 centroids [K,256], weight [B]
//   c = normalize(centroids, dim=1)
//   prod = features @ c.T / 0.07   -> per-row max m[b], argmax pos[b]
//   S[k] = sum_j exp((c @ c.T / 0.07)[j,k])
//   pep = exp(m)*w ; J = logf(pep) - logf(pep + S[pos]) ; out = -mean(J)
//
// sm_100 target (no tcgen05): classic bf16 mma.sync.m16n8k16 + ldmatrix +
// cp.async double-buffered. Fused GEMM X=[features; c] (12288x256) @ c.T,
// CTA tile 128x128, K in 8 chunks of 32.
// R4 changes: smem 40960B (< 48K default -> NO cudaFuncSetAttribute, no
// silent launch-failure path), NaN-proof final decode, zero-fill out tail.
// ============================================================================

#define B_ROWS 4096
#define K_ROWS 8192
#define D_DIM  256
#define X_ROWS (B_ROWS + K_ROWS)
#define TILE   128
#define INV_T  14.285714285714285714f  // 1/0.07

// smem chunk: 128 rows x 32 cols bf16 (64B) padded to 80B rows
#define ROW_BYTES  80
#define CHUNK_BYTES (TILE * ROW_BYTES)            // 10240
#define STAGE_BYTES (2 * CHUNK_BYTES)             // A + B one stage = 20480
#define SMEM_BYTES  (2 * STAGE_BYTES)             // 40960  (< 48K)
#define NCHUNK 8                                  // 8 x 32 = K=256

__device__ __nv_bfloat16 g_X[(size_t)X_ROWS * D_DIM];   // [features; c_normalized]
__device__ float g_S[K_ROWS];
__device__ unsigned long long g_max[B_ROWS];            // packed (ordered-float, ~col)

// ---------------- helpers ----------------------------------------------------

static __device__ __forceinline__ uint32_t smem_u32(const void* p) {
    uint32_t a;
    asm("{ .reg .u64 t; cvta.to.shared.u64 t, %1; cvt.u32.u64 %0, t; }"
        : "=r"(a) : "l"(p));
    return a;
}

static __device__ __forceinline__ void cp16(uint32_t dst, const void* src) {
    asm volatile("cp.async.cg.shared.global [%0], [%1], 16;"
                 :: "r"(dst), "l"(src));
}

static __device__ __forceinline__ void ldsm4(uint32_t& r0, uint32_t& r1,
                                             uint32_t& r2, uint32_t& r3,
                                             uint32_t addr) {
    asm volatile("ldmatrix.sync.aligned.m8n8.x4.shared.b16 {%0,%1,%2,%3}, [%4];"
                 : "=r"(r0), "=r"(r1), "=r"(r2), "=r"(r3) : "r"(addr));
}

static __device__ __forceinline__ void mma16816(float* c, const uint32_t* a,
                                                const uint32_t* b) {
    asm volatile(
        "mma.sync.aligned.m16n8k16.row.col.f32.bf16.bf16.f32 "
        "{%0,%1,%2,%3}, {%4,%5,%6,%7}, {%8,%9}, {%0,%1,%2,%3};"
        : "+f"(c[0]), "+f"(c[1]), "+f"(c[2]), "+f"(c[3])
        : "r"(a[0]), "r"(a[1]), "r"(a[2]), "r"(a[3]), "r"(b[0]), "r"(b[1]));
}

// ---------------- prep kernels ----------------------------------------------

__global__ void k_init() {
    int i = blockIdx.x * blockDim.x + threadIdx.x;
    if (i < K_ROWS) g_S[i] = 0.0f;
    if (i < B_ROWS) g_max[i] = 0ull;
}

__global__ void k_feat(const float* __restrict__ f) {
    int i = blockIdx.x * blockDim.x + threadIdx.x;   // exactly 4096*256 threads
    g_X[i] = __float2bfloat16(f[i]);
}

__global__ void k_norm(const float* __restrict__ cent) {
    __shared__ float ws[8];
    __shared__ float sc;
    int k = blockIdx.x, t = threadIdx.x;             // 256 threads, one row
    float v = cent[(size_t)k * D_DIM + t];
    float s = v * v;
    #pragma unroll
    for (int o = 16; o; o >>= 1) s += __shfl_xor_sync(~0u, s, o);
    if ((t & 31) == 0) ws[t >> 5] = s;
    __syncthreads();
    if (t == 0) {
        float tot = 0.0f;
        #pragma unroll
        for (int i = 0; i < 8; i++) tot += ws[i];
        sc = 1.0f / fmaxf(sqrtf(tot), 1e-12f);
    }
    __syncthreads();
    g_X[(size_t)(B_ROWS + k) * D_DIM + t] = __float2bfloat16(v * sc);
}

// ---------------- fused GEMM + epilogue --------------------------------------
// grid = (96, 64). 256 threads = 8 warps, warp grid 2(M) x 4(N), warp tile 64x32.

__global__ void __launch_bounds__(256, 2) k_gemm() {
    extern __shared__ char smem[];
    const uint32_t sb = smem_u32(smem);
    const int tid = threadIdx.x;
    const int wid = tid >> 5, lid = tid & 31;
    const int wm = wid >> 2, wn = wid & 3;           // warp coords
    const int mtile = blockIdx.x, ntile = blockIdx.y;

    const __nv_bfloat16* gA = g_X + (size_t)mtile * TILE * D_DIM;
    const __nv_bfloat16* gB = g_X + (size_t)(B_ROWS + ntile * TILE) * D_DIM;

    float acc[4][4][4];
    #pragma unroll
    for (int a = 0; a < 4; a++)
        #pragma unroll
        for (int b = 0; b < 4; b++)
            #pragma unroll
            for (int i = 0; i < 4; i++) acc[a][b][i] = 0.0f;

    // ---- prefetch chunk 0: per tile 128 rows x 64B = 512 x 16B transfers ----
    #pragma unroll
    for (int i = 0; i < 2; i++) {
        int idx = tid + i * 256;                 // 0..511
        int row = idx >> 2, colc = idx & 3;      // row 0..127, colc 0..3
        uint32_t so = sb + (uint32_t)(row * ROW_BYTES + colc * 16);
        cp16(so, gA + (size_t)row * D_DIM + colc * 8);
        cp16(so + CHUNK_BYTES, gB + (size_t)row * D_DIM + colc * 8);
    }
    asm volatile("cp.async.commit_group;" ::: "memory");

    // ldmatrix address components (per lane)
    const int arow = lid & 15, asel = lid >> 4;
    const int brow = lid & 7;
    const int bsel = lid >> 3;
    const int bn_off = 8 * (bsel >> 1), bk_off = 8 * (bsel & 1);

    #pragma unroll
    for (int kc = 0; kc < NCHUNK; kc++) {
        if (kc < NCHUNK - 1) {
            int nk = kc + 1;
            uint32_t stage = (uint32_t)(nk & 1) * STAGE_BYTES;
            #pragma unroll
            for (int i = 0; i < 2; i++) {
                int idx = tid + i * 256;
                int row = idx >> 2, colc = idx & 3;
                uint32_t so = sb + stage + (uint32_t)(row * ROW_BYTES + colc * 16);
                cp16(so, gA + (size_t)row * D_DIM + nk * 32 + colc * 8);
                cp16(so + CHUNK_BYTES, gB + (size_t)row * D_DIM + nk * 32 + colc * 8);
            }
            asm volatile("cp.async.commit_group;" ::: "memory");
            asm volatile("cp.async.wait_group 1;" ::: "memory");
        } else {
            asm volatile("cp.async.wait_group 0;" ::: "memory");
        }
        __syncthreads();

        const uint32_t sA = sb + (uint32_t)(kc & 1) * STAGE_BYTES;
        const uint32_t sB = sA + CHUNK_BYTES;

        #pragma unroll
        for (int ks = 0; ks < 2; ks++) {
            const int k0 = ks * 16;
            uint32_t a[4][4];
            #pragma unroll
            for (int mf = 0; mf < 4; mf++) {
                uint32_t ad = sA + (uint32_t)((wm * 64 + mf * 16 + arow) * ROW_BYTES
                                              + (k0 + 8 * asel) * 2);
                ldsm4(a[mf][0], a[mf][1], a[mf][2], a[mf][3], ad);
            }
            uint32_t b[4][2];
            #pragma unroll
            for (int half = 0; half < 2; half++) {
                int n0 = wn * 32 + half * 16;
                uint32_t bd = sB + (uint32_t)((n0 + bn_off + brow) * ROW_BYTES
                                              + (k0 + bk_off) * 2);
                ldsm4(b[half * 2][0], b[half * 2][1],
                      b[half * 2 + 1][0], b[half * 2 + 1][1], bd);
            }
            #pragma unroll
            for (int mf = 0; mf < 4; mf++)
                #pragma unroll
                for (int nf = 0; nf < 4; nf++)
                    mma16816(acc[mf][nf], a[mf], b[nf]);
        }
        __syncthreads();
    }

    // ---- epilogue ----
    const int quad = lid & 3, g = lid >> 2;
    if (mtile < (B_ROWS / TILE)) {
        // feature rows: per-row max + argmax
        #pragma unroll
        for (int mf = 0; mf < 4; mf++) {
            #pragma unroll
            for (int h = 0; h < 2; h++) {
                float best = -3.4e38f;
                int bc = 0;
                #pragma unroll
                for (int nf = 0; nf < 4; nf++) {
                    #pragma unroll
                    for (int j = 0; j < 2; j++) {
                        float v = acc[mf][nf][2 * h + j] * INV_T;
                        int col = ntile * TILE + wn * 32 + nf * 8 + quad * 2 + j;
                        if (v > best || (v == best && col < bc)) { best = v; bc = col; }
                    }
                }
                #pragma unroll
                for (int m = 1; m <= 2; m <<= 1) {
                    float ov = __shfl_xor_sync(~0u, best, m);
                    int oc = __shfl_xor_sync(~0u, bc, m);
                    if (ov > best || (ov == best && oc < bc)) { best = ov; bc = oc; }
                }
                if (quad == 0) {
                    int row = mtile * TILE + wm * 64 + mf * 16 + g + 8 * h;
                    unsigned bits = __float_as_uint(best);
                    unsigned u = (bits & 0x80000000u) ? ~bits : (bits | 0x80000000u);
                    unsigned long long packed =
                        ((unsigned long long)u << 32) |
                        (unsigned long long)(0xFFFFFFFFu - (unsigned)bc);
                    atomicMax(&g_max[row], packed);
                }
            }
        }
    } else {
        // centroid rows: exp + column-sum (each warp adds its 64-row partial)
        #pragma unroll
        for (int nf = 0; nf < 4; nf++) {
            #pragma unroll
            for (int j = 0; j < 2; j++) {
                float s = 0.0f;
                #pragma unroll
                for (int mf = 0; mf < 4; mf++) {
                    s += __expf(acc[mf][nf][j] * INV_T);
                    s += __expf(acc[mf][nf][2 + j] * INV_T);
                }
                #pragma unroll
                for (int m = 4; m <= 16; m <<= 1)
                    s += __shfl_xor_sync(~0u, s, m);
                if (g == 0)
                    atomicAdd(&g_S[ntile * TILE + wn * 32 + nf * 8 + quad * 2 + j], s);
            }
        }
    }
}

// ---------------- final scalar reduction -------------------------------------
// Replicates the reference fp32 math: J = logf(pep) - logf(pep + S).
// NaN-proofed: unwritten g_max (p==0) or non-finite J contributes 0.

__global__ void k_final(const float* __restrict__ w, float* __restrict__ out,
                        int out_size) {
    __shared__ float part[256];
    int t = threadIdx.x;
    float acc = 0.0f;
    for (int b = t; b < B_ROWS; b += 256) {
        unsigned long long p = g_max[b];
        float J = 0.0f;
        if (p != 0ull) {
            unsigned u = (unsigned)(p >> 32);
            int col = (int)(0xFFFFFFFFu - (unsigned)(p & 0xFFFFFFFFull));
            float m = (u & 0x80000000u) ? __uint_as_float(u & 0x7FFFFFFFu)
                                        : __uint_as_float(~u);
            float pep = expf(m) * w[b];
            float Sv  = (col >= 0 && col < K_ROWS) ? g_S[col] : 0.0f;
            J = logf(pep) - logf(pep + Sv);
            if (isnan(J)) J = 0.0f;
        }
        acc += J;
    }
    part[t] = acc;
    __syncthreads();
    #pragma unroll
    for (int o = 128; o; o >>= 1) {
        if (t < o) part[t] += part[t + o];
        __syncthreads();
    }
    if (t == 0) out[0] = -(part[0] / (float)B_ROWS);
    // zero any extra output elements (poisoned 0xAA otherwise)
    for (int i = 1 + t; i < out_size; i += 256) out[i] = 0.0f;
}

// ---------------- launch ------------------------------------------------------

extern "C" void kernel_launch(void* const* d_in, const int* in_sizes, int n_in,
                              void* d_out, int out_size) {
    // Bind inputs BY SIZE (robust to metadata ordering):
    //   features: 1048576, centroids: 2097152, weight: 4096
    const float* features  = nullptr;
    const float* centroids = nullptr;
    const float* weight    = nullptr;
    for (int i = 0; i < n_in; i++) {
        if (in_sizes[i] == B_ROWS * D_DIM)      features  = (const float*)d_in[i];
        else if (in_sizes[i] == K_ROWS * D_DIM) centroids = (const float*)d_in[i];
        else if (in_sizes[i] == B_ROWS)         weight    = (const float*)d_in[i];
    }
    float* out = (float*)d_out;

    k_init<<<32, 256>>>();
    k_feat<<<(B_ROWS * D_DIM) / 256, 256>>>(features);
    k_norm<<<K_ROWS, 256>>>(centroids);

    dim3 grid(X_ROWS / TILE, K_ROWS / TILE);   // (96, 64)
    k_gemm<<<grid, 256, SMEM_BYTES>>>();       // 40960 B < 48K: no attribute call

    k_final<<<1, 256>>>(weight, out, out_size);
}

// round 6
// speedup vs baseline: 1.2929x; 1.2929x over previous
#include <cuda_runtime.h>
#include <cuda_bf16.h>
#include <cstdint>

// ============================================================================
// B=4096 features [B,256], K=8192 centroids [K,256], weight [B]
//   c = normalize(centroids, dim=1)
//   prod = features @ c.T / 0.07   -> per-row max m[b], argmax pos[b]
//   S[k] = sum_j exp((c @ c.T / 0.07)[j,k])
//   pep = exp(m)*w ; J = logf(pep) - logf(pep + S[pos]) ; out = -mean(J)
//
// sm_100 target: classic bf16 mma.sync.m16n8k16 + ldmatrix + cp.async
// double-buffered. Fused GEMM X=[features; c] @ c.T, CTA tile 128x128.
// R5 -> R6: exploit symmetry of c@c.T. Off-diagonal centroid tiles (i<j)
// are computed once; column sums feed S[j-block], row sums feed S[i-block].
// Lower-triangle CTAs exit immediately. 6144 -> 4128 working tiles.
// ============================================================================

#define B_ROWS 4096
#define K_ROWS 8192
#define D_DIM  256
#define X_ROWS (B_ROWS + K_ROWS)
#define TILE   128
#define FTILES (B_ROWS / TILE)                    // 32 feature m-tiles
#define INV_T  14.285714285714285714f             // 1/0.07

// smem chunk: 128 rows x 32 cols bf16 (64B) padded to 80B rows
#define ROW_BYTES  80
#define CHUNK_BYTES (TILE * ROW_BYTES)            // 10240
#define STAGE_BYTES (2 * CHUNK_BYTES)             // 20480
#define SMEM_BYTES  (2 * STAGE_BYTES)             // 40960 (< 48K, no attribute)
#define NCHUNK 8                                  // 8 x 32 = K=256

__device__ __nv_bfloat16 g_X[(size_t)X_ROWS * D_DIM];   // [features; c_normalized]
__device__ float g_S[K_ROWS];
__device__ unsigned long long g_max[B_ROWS];            // packed (ordered-float, ~col)

// ---------------- helpers ----------------------------------------------------

static __device__ __forceinline__ uint32_t smem_u32(const void* p) {
    uint32_t a;
    asm("{ .reg .u64 t; cvta.to.shared.u64 t, %1; cvt.u32.u64 %0, t; }"
        : "=r"(a) : "l"(p));
    return a;
}

static __device__ __forceinline__ void cp16(uint32_t dst, const void* src) {
    asm volatile("cp.async.cg.shared.global [%0], [%1], 16;"
                 :: "r"(dst), "l"(src));
}

static __device__ __forceinline__ void ldsm4(uint32_t& r0, uint32_t& r1,
                                             uint32_t& r2, uint32_t& r3,
                                             uint32_t addr) {
    asm volatile("ldmatrix.sync.aligned.m8n8.x4.shared.b16 {%0,%1,%2,%3}, [%4];"
                 : "=r"(r0), "=r"(r1), "=r"(r2), "=r"(r3) : "r"(addr));
}

static __device__ __forceinline__ void mma16816(float* c, const uint32_t* a,
                                                const uint32_t* b) {
    asm volatile(
        "mma.sync.aligned.m16n8k16.row.col.f32.bf16.bf16.f32 "
        "{%0,%1,%2,%3}, {%4,%5,%6,%7}, {%8,%9}, {%0,%1,%2,%3};"
        : "+f"(c[0]), "+f"(c[1]), "+f"(c[2]), "+f"(c[3])
        : "r"(a[0]), "r"(a[1]), "r"(a[2]), "r"(a[3]), "r"(b[0]), "r"(b[1]));
}

// ---------------- prep kernels ----------------------------------------------

__global__ void k_init() {
    int i = blockIdx.x * blockDim.x + threadIdx.x;
    if (i < K_ROWS) g_S[i] = 0.0f;
    if (i < B_ROWS) g_max[i] = 0ull;
}

__global__ void k_feat(const float* __restrict__ f) {
    int i = blockIdx.x * blockDim.x + threadIdx.x;   // exactly 4096*256 threads
    g_X[i] = __float2bfloat16(f[i]);
}

__global__ void k_norm(const float* __restrict__ cent) {
    __shared__ float ws[8];
    __shared__ float sc;
    int k = blockIdx.x, t = threadIdx.x;             // 256 threads, one row
    float v = cent[(size_t)k * D_DIM + t];
    float s = v * v;
    #pragma unroll
    for (int o = 16; o; o >>= 1) s += __shfl_xor_sync(~0u, s, o);
    if ((t & 31) == 0) ws[t >> 5] = s;
    __syncthreads();
    if (t == 0) {
        float tot = 0.0f;
        #pragma unroll
        for (int i = 0; i < 8; i++) tot += ws[i];
        sc = 1.0f / fmaxf(sqrtf(tot), 1e-12f);
    }
    __syncthreads();
    g_X[(size_t)(B_ROWS + k) * D_DIM + t] = __float2bfloat16(v * sc);
}

// ---------------- fused GEMM + epilogue --------------------------------------
// grid = (96, 64). 256 threads = 8 warps, warp grid 2(M) x 4(N), warp tile 64x32.
// mtile < 32: feature rows. mtile >= 32: centroid row-tile i = mtile-32;
// lower triangle (i > ntile) exits; i < ntile gets a dual (col+row) epilogue.

__global__ void __launch_bounds__(256, 2) k_gemm() {
    const int mtile = blockIdx.x, ntile = blockIdx.y;
    const bool is_feat = (mtile < FTILES);
    const int ctile = mtile - FTILES;                // centroid row-tile index
    if (!is_feat && ctile > ntile) return;           // symmetric half: skip

    extern __shared__ char smem[];
    const uint32_t sb = smem_u32(smem);
    const int tid = threadIdx.x;
    const int wid = tid >> 5, lid = tid & 31;
    const int wm = wid >> 2, wn = wid & 3;           // warp coords

    const __nv_bfloat16* gA = g_X + (size_t)mtile * TILE * D_DIM;
    const __nv_bfloat16* gB = g_X + (size_t)(B_ROWS + ntile * TILE) * D_DIM;

    float acc[4][4][4];
    #pragma unroll
    for (int a = 0; a < 4; a++)
        #pragma unroll
        for (int b = 0; b < 4; b++)
            #pragma unroll
            for (int i = 0; i < 4; i++) acc[a][b][i] = 0.0f;

    // ---- prefetch chunk 0: per tile 128 rows x 64B = 512 x 16B transfers ----
    #pragma unroll
    for (int i = 0; i < 2; i++) {
        int idx = tid + i * 256;                 // 0..511
        int row = idx >> 2, colc = idx & 3;      // row 0..127, colc 0..3
        uint32_t so = sb + (uint32_t)(row * ROW_BYTES + colc * 16);
        cp16(so, gA + (size_t)row * D_DIM + colc * 8);
        cp16(so + CHUNK_BYTES, gB + (size_t)row * D_DIM + colc * 8);
    }
    asm volatile("cp.async.commit_group;" ::: "memory");

    // ldmatrix address components (per lane)
    const int arow = lid & 15, asel = lid >> 4;
    const int brow = lid & 7;
    const int bsel = lid >> 3;
    const int bn_off = 8 * (bsel >> 1), bk_off = 8 * (bsel & 1);

    #pragma unroll
    for (int kc = 0; kc < NCHUNK; kc++) {
        if (kc < NCHUNK - 1) {
            int nk = kc + 1;
            uint32_t stage = (uint32_t)(nk & 1) * STAGE_BYTES;
            #pragma unroll
            for (int i = 0; i < 2; i++) {
                int idx = tid + i * 256;
                int row = idx >> 2, colc = idx & 3;
                uint32_t so = sb + stage + (uint32_t)(row * ROW_BYTES + colc * 16);
                cp16(so, gA + (size_t)row * D_DIM + nk * 32 + colc * 8);
                cp16(so + CHUNK_BYTES, gB + (size_t)row * D_DIM + nk * 32 + colc * 8);
            }
            asm volatile("cp.async.commit_group;" ::: "memory");
            asm volatile("cp.async.wait_group 1;" ::: "memory");
        } else {
            asm volatile("cp.async.wait_group 0;" ::: "memory");
        }
        __syncthreads();

        const uint32_t sA = sb + (uint32_t)(kc & 1) * STAGE_BYTES;
        const uint32_t sB = sA + CHUNK_BYTES;

        #pragma unroll
        for (int ks = 0; ks < 2; ks++) {
            const int k0 = ks * 16;
            uint32_t a[4][4];
            #pragma unroll
            for (int mf = 0; mf < 4; mf++) {
                uint32_t ad = sA + (uint32_t)((wm * 64 + mf * 16 + arow) * ROW_BYTES
                                              + (k0 + 8 * asel) * 2);
                ldsm4(a[mf][0], a[mf][1], a[mf][2], a[mf][3], ad);
            }
            uint32_t b[4][2];
            #pragma unroll
            for (int half = 0; half < 2; half++) {
                int n0 = wn * 32 + half * 16;
                uint32_t bd = sB + (uint32_t)((n0 + bn_off + brow) * ROW_BYTES
                                              + (k0 + bk_off) * 2);
                ldsm4(b[half * 2][0], b[half * 2][1],
                      b[half * 2 + 1][0], b[half * 2 + 1][1], bd);
            }
            #pragma unroll
            for (int mf = 0; mf < 4; mf++)
                #pragma unroll
                for (int nf = 0; nf < 4; nf++)
                    mma16816(acc[mf][nf], a[mf], b[nf]);
        }
        __syncthreads();
    }

    // ---- epilogue ----
    const int quad = lid & 3, g = lid >> 2;
    if (is_feat) {
        // feature rows: per-row max + argmax
        #pragma unroll
        for (int mf = 0; mf < 4; mf++) {
            #pragma unroll
            for (int h = 0; h < 2; h++) {
                float best = -3.4e38f;
                int bc = 0;
                #pragma unroll
                for (int nf = 0; nf < 4; nf++) {
                    #pragma unroll
                    for (int j = 0; j < 2; j++) {
                        float v = acc[mf][nf][2 * h + j] * INV_T;
                        int col = ntile * TILE + wn * 32 + nf * 8 + quad * 2 + j;
                        if (v > best || (v == best && col < bc)) { best = v; bc = col; }
                    }
                }
                #pragma unroll
                for (int m = 1; m <= 2; m <<= 1) {
                    float ov = __shfl_xor_sync(~0u, best, m);
                    int oc = __shfl_xor_sync(~0u, bc, m);
                    if (ov > best || (ov == best && oc < bc)) { best = ov; bc = oc; }
                }
                if (quad == 0) {
                    int row = mtile * TILE + wm * 64 + mf * 16 + g + 8 * h;
                    unsigned bits = __float_as_uint(best);
                    unsigned u = (bits & 0x80000000u) ? ~bits : (bits | 0x80000000u);
                    unsigned long long packed =
                        ((unsigned long long)u << 32) |
                        (unsigned long long)(0xFFFFFFFFu - (unsigned)bc);
                    atomicMax(&g_max[row], packed);
                }
            }
        }
    } else {
        // centroid tile (ctile <= ntile): column sums always.
        #pragma unroll
        for (int nf = 0; nf < 4; nf++) {
            #pragma unroll
            for (int j = 0; j < 2; j++) {
                float s = 0.0f;
                #pragma unroll
                for (int mf = 0; mf < 4; mf++) {
                    s += __expf(acc[mf][nf][j] * INV_T);
                    s += __expf(acc[mf][nf][2 + j] * INV_T);
                }
                #pragma unroll
                for (int m = 4; m <= 16; m <<= 1)
                    s += __shfl_xor_sync(~0u, s, m);
                if (g == 0)
                    atomicAdd(&g_S[ntile * TILE + wn * 32 + nf * 8 + quad * 2 + j], s);
            }
        }
        // off-diagonal: row sums stand in for the skipped transposed tile.
        if (ctile < ntile) {
            #pragma unroll
            for (int mf = 0; mf < 4; mf++) {
                #pragma unroll
                for (int h = 0; h < 2; h++) {
                    float s = 0.0f;
                    #pragma unroll
                    for (int nf = 0; nf < 4; nf++) {
                        s += __expf(acc[mf][nf][2 * h + 0] * INV_T);
                        s += __expf(acc[mf][nf][2 * h + 1] * INV_T);
                    }
                    // reduce across quad lanes (cols) within the warp
                    #pragma unroll
                    for (int m = 1; m <= 2; m <<= 1)
                        s += __shfl_xor_sync(~0u, s, m);
                    if (quad == 0)
                        atomicAdd(&g_S[ctile * TILE + wm * 64 + mf * 16 + g + 8 * h], s);
                }
            }
        }
    }
}

// ---------------- final scalar reduction -------------------------------------
// Replicates the reference fp32 math: J = logf(pep) - logf(pep + S).
// NaN-proofed: unwritten g_max (p==0) or non-finite J contributes 0.

__global__ void k_final(const float* __restrict__ w, float* __restrict__ out,
                        int out_size) {
    __shared__ float part[256];
    int t = threadIdx.x;
    float acc = 0.0f;
    for (int b = t; b < B_ROWS; b += 256) {
        unsigned long long p = g_max[b];
        float J = 0.0f;
        if (p != 0ull) {
            unsigned u = (unsigned)(p >> 32);
            int col = (int)(0xFFFFFFFFu - (unsigned)(p & 0xFFFFFFFFull));
            float m = (u & 0x80000000u) ? __uint_as_float(u & 0x7FFFFFFFu)
                                        : __uint_as_float(~u);
            float pep = expf(m) * w[b];
            float Sv  = (col >= 0 && col < K_ROWS) ? g_S[col] : 0.0f;
            J = logf(pep) - logf(pep + Sv);
            if (isnan(J)) J = 0.0f;
        }
        acc += J;
    }
    part[t] = acc;
    __syncthreads();
    #pragma unroll
    for (int o = 128; o; o >>= 1) {
        if (t < o) part[t] += part[t + o];
        __syncthreads();
    }
    if (t == 0) out[0] = -(part[0] / (float)B_ROWS);
    for (int i = 1 + t; i < out_size; i += 256) out[i] = 0.0f;
}

// ---------------- launch ------------------------------------------------------

extern "C" void kernel_launch(void* const* d_in, const int* in_sizes, int n_in,
                              void* d_out, int out_size) {
    // Bind inputs BY SIZE (robust to metadata ordering):
    //   features: 1048576, centroids: 2097152, weight: 4096
    const float* features  = nullptr;
    const float* centroids = nullptr;
    const float* weight    = nullptr;
    for (int i = 0; i < n_in; i++) {
        if (in_sizes[i] == B_ROWS * D_DIM)      features  = (const float*)d_in[i];
        else if (in_sizes[i] == K_ROWS * D_DIM) centroids = (const float*)d_in[i];
        else if (in_sizes[i] == B_ROWS)         weight    = (const float*)d_in[i];
    }
    float* out = (float*)d_out;

    k_init<<<32, 256>>>();
    k_feat<<<(B_ROWS * D_DIM) / 256, 256>>>(features);
    k_norm<<<K_ROWS, 256>>>(centroids);

    dim3 grid(X_ROWS / TILE, K_ROWS / TILE);   // (96, 64); lower triangle exits
    k_gemm<<<grid, 256, SMEM_BYTES>>>();

    k_final<<<1, 256>>>(weight, out, out_size);
}

// round 7
// speedup vs baseline: 1.3276x; 1.0269x over previous
#include <cuda_runtime.h>
#include <cuda_bf16.h>
#include <cstdint>

// ============================================================================
// B=4096 features [B,256], K=8192 centroids [K,256], weight [B]
//   c = normalize(centroids, dim=1)
//   prod = features @ c.T / 0.07   -> per-row max m[b], argmax pos[b]
//   S[k] = sum_j exp((c @ c.T / 0.07)[j,k])
//   pep = exp(m)*w ; J = logf(pep) - logf(pep + S[pos]) ; out = -mean(J)
//
// sm_100 target: classic bf16 mma.sync.m16n8k16 + ldmatrix + cp.async
// double-buffered. Fused GEMM X=[features; c] @ c.T, CTA tile 128x128,
// symmetric half of c@c.T skipped (dual col+row-sum epilogue).
// R6 -> R7: single __syncthreads per K-chunk (8 barriers/tile instead of 16):
//   wait_group 0 ; sync ; issue cp.async(kc+1) ; compute(kc)
// The one sync both publishes chunk kc and retires all reads of the buffer
// that cp.async(kc+1) is about to overwrite (last read in iter kc-1).
// ============================================================================

#define B_ROWS 4096
#define K_ROWS 8192
#define D_DIM  256
#define X_ROWS (B_ROWS + K_ROWS)
#define TILE   128
#define FTILES (B_ROWS / TILE)                    // 32 feature m-tiles
#define INV_T  14.285714285714285714f             // 1/0.07

// smem chunk: 128 rows x 32 cols bf16 (64B) padded to 80B rows
#define ROW_BYTES  80
#define CHUNK_BYTES (TILE * ROW_BYTES)            // 10240
#define STAGE_BYTES (2 * CHUNK_BYTES)             // 20480
#define SMEM_BYTES  (2 * STAGE_BYTES)             // 40960 (< 48K, no attribute)
#define NCHUNK 8                                  // 8 x 32 = K=256

__device__ __nv_bfloat16 g_X[(size_t)X_ROWS * D_DIM];   // [features; c_normalized]
__device__ float g_S[K_ROWS];
__device__ unsigned long long g_max[B_ROWS];            // packed (ordered-float, ~col)

// ---------------- helpers ----------------------------------------------------

static __device__ __forceinline__ uint32_t smem_u32(const void* p) {
    uint32_t a;
    asm("{ .reg .u64 t; cvta.to.shared.u64 t, %1; cvt.u32.u64 %0, t; }"
        : "=r"(a) : "l"(p));
    return a;
}

static __device__ __forceinline__ void cp16(uint32_t dst, const void* src) {
    asm volatile("cp.async.cg.shared.global [%0], [%1], 16;"
                 :: "r"(dst), "l"(src));
}

static __device__ __forceinline__ void ldsm4(uint32_t& r0, uint32_t& r1,
                                             uint32_t& r2, uint32_t& r3,
                                             uint32_t addr) {
    asm volatile("ldmatrix.sync.aligned.m8n8.x4.shared.b16 {%0,%1,%2,%3}, [%4];"
                 : "=r"(r0), "=r"(r1), "=r"(r2), "=r"(r3) : "r"(addr));
}

static __device__ __forceinline__ void mma16816(float* c, const uint32_t* a,
                                                const uint32_t* b) {
    asm volatile(
        "mma.sync.aligned.m16n8k16.row.col.f32.bf16.bf16.f32 "
        "{%0,%1,%2,%3}, {%4,%5,%6,%7}, {%8,%9}, {%0,%1,%2,%3};"
        : "+f"(c[0]), "+f"(c[1]), "+f"(c[2]), "+f"(c[3])
        : "r"(a[0]), "r"(a[1]), "r"(a[2]), "r"(a[3]), "r"(b[0]), "r"(b[1]));
}

// ---------------- prep kernels ----------------------------------------------

__global__ void k_init() {
    int i = blockIdx.x * blockDim.x + threadIdx.x;
    if (i < K_ROWS) g_S[i] = 0.0f;
    if (i < B_ROWS) g_max[i] = 0ull;
}

__global__ void k_feat(const float* __restrict__ f) {
    int i = blockIdx.x * blockDim.x + threadIdx.x;   // exactly 4096*256 threads
    g_X[i] = __float2bfloat16(f[i]);
}

__global__ void k_norm(const float* __restrict__ cent) {
    __shared__ float ws[8];
    __shared__ float sc;
    int k = blockIdx.x, t = threadIdx.x;             // 256 threads, one row
    float v = cent[(size_t)k * D_DIM + t];
    float s = v * v;
    #pragma unroll
    for (int o = 16; o; o >>= 1) s += __shfl_xor_sync(~0u, s, o);
    if ((t & 31) == 0) ws[t >> 5] = s;
    __syncthreads();
    if (t == 0) {
        float tot = 0.0f;
        #pragma unroll
        for (int i = 0; i < 8; i++) tot += ws[i];
        sc = 1.0f / fmaxf(sqrtf(tot), 1e-12f);
    }
    __syncthreads();
    g_X[(size_t)(B_ROWS + k) * D_DIM + t] = __float2bfloat16(v * sc);
}

// ---------------- fused GEMM + epilogue --------------------------------------
// grid = (96, 64). 256 threads = 8 warps, warp grid 2(M) x 4(N), warp tile 64x32.

__global__ void __launch_bounds__(256, 2) k_gemm() {
    const int mtile = blockIdx.x, ntile = blockIdx.y;
    const bool is_feat = (mtile < FTILES);
    const int ctile = mtile - FTILES;                // centroid row-tile index
    if (!is_feat && ctile > ntile) return;           // symmetric half: skip

    extern __shared__ char smem[];
    const uint32_t sb = smem_u32(smem);
    const int tid = threadIdx.x;
    const int wid = tid >> 5, lid = tid & 31;
    const int wm = wid >> 2, wn = wid & 3;           // warp coords

    const __nv_bfloat16* gA = g_X + (size_t)mtile * TILE * D_DIM;
    const __nv_bfloat16* gB = g_X + (size_t)(B_ROWS + ntile * TILE) * D_DIM;

    float acc[4][4][4];
    #pragma unroll
    for (int a = 0; a < 4; a++)
        #pragma unroll
        for (int b = 0; b < 4; b++)
            #pragma unroll
            for (int i = 0; i < 4; i++) acc[a][b][i] = 0.0f;

    // per-thread cp coords: 512 x 16B per tile; row = idx/4, colc = idx%4
    const int r0c = tid >> 2, c0c = tid & 3;          // idx = tid
    const int r1c = (tid + 256) >> 2, c1c = tid & 3;  // idx = tid + 256

    // ---- prefetch chunk 0 ----
    {
        uint32_t so0 = sb + (uint32_t)(r0c * ROW_BYTES + c0c * 16);
        uint32_t so1 = sb + (uint32_t)(r1c * ROW_BYTES + c1c * 16);
        cp16(so0, gA + (size_t)r0c * D_DIM + c0c * 8);
        cp16(so0 + CHUNK_BYTES, gB + (size_t)r0c * D_DIM + c0c * 8);
        cp16(so1, gA + (size_t)r1c * D_DIM + c1c * 8);
        cp16(so1 + CHUNK_BYTES, gB + (size_t)r1c * D_DIM + c1c * 8);
    }
    asm volatile("cp.async.commit_group;" ::: "memory");

    // ldmatrix address components (per lane)
    const int arow = lid & 15, asel = lid >> 4;
    const int brow = lid & 7;
    const int bsel = lid >> 3;
    const int bn_off = 8 * (bsel >> 1), bk_off = 8 * (bsel & 1);

    #pragma unroll
    for (int kc = 0; kc < NCHUNK; kc++) {
        // wait for chunk kc, publish it, retire all reads of stage (kc+1)&1
        asm volatile("cp.async.wait_group 0;" ::: "memory");
        __syncthreads();

        // issue loads for chunk kc+1 into the buffer everyone just finished with
        if (kc < NCHUNK - 1) {
            const int nk = kc + 1;
            const uint32_t stage = (uint32_t)(nk & 1) * STAGE_BYTES;
            uint32_t so0 = sb + stage + (uint32_t)(r0c * ROW_BYTES + c0c * 16);
            uint32_t so1 = sb + stage + (uint32_t)(r1c * ROW_BYTES + c1c * 16);
            cp16(so0, gA + (size_t)r0c * D_DIM + nk * 32 + c0c * 8);
            cp16(so0 + CHUNK_BYTES, gB + (size_t)r0c * D_DIM + nk * 32 + c0c * 8);
            cp16(so1, gA + (size_t)r1c * D_DIM + nk * 32 + c1c * 8);
            cp16(so1 + CHUNK_BYTES, gB + (size_t)r1c * D_DIM + nk * 32 + c1c * 8);
            asm volatile("cp.async.commit_group;" ::: "memory");
        }

        const uint32_t sA = sb + (uint32_t)(kc & 1) * STAGE_BYTES;
        const uint32_t sB = sA + CHUNK_BYTES;

        #pragma unroll
        for (int ks = 0; ks < 2; ks++) {
            const int k0 = ks * 16;
            uint32_t a[4][4];
            #pragma unroll
            for (int mf = 0; mf < 4; mf++) {
                uint32_t ad = sA + (uint32_t)((wm * 64 + mf * 16 + arow) * ROW_BYTES
                                              + (k0 + 8 * asel) * 2);
                ldsm4(a[mf][0], a[mf][1], a[mf][2], a[mf][3], ad);
            }
            uint32_t b[4][2];
            #pragma unroll
            for (int half = 0; half < 2; half++) {
                int n0 = wn * 32 + half * 16;
                uint32_t bd = sB + (uint32_t)((n0 + bn_off + brow) * ROW_BYTES
                                              + (k0 + bk_off) * 2);
                ldsm4(b[half * 2][0], b[half * 2][1],
                      b[half * 2 + 1][0], b[half * 2 + 1][1], bd);
            }
            #pragma unroll
            for (int mf = 0; mf < 4; mf++)
                #pragma unroll
                for (int nf = 0; nf < 4; nf++)
                    mma16816(acc[mf][nf], a[mf], b[nf]);
        }
    }

    // ---- epilogue ----
    const int quad = lid & 3, g = lid >> 2;
    if (is_feat) {
        // feature rows: per-row max + argmax
        #pragma unroll
        for (int mf = 0; mf < 4; mf++) {
            #pragma unroll
            for (int h = 0; h < 2; h++) {
                float best = -3.4e38f;
                int bc = 0;
                #pragma unroll
                for (int nf = 0; nf < 4; nf++) {
                    #pragma unroll
                    for (int j = 0; j < 2; j++) {
                        float v = acc[mf][nf][2 * h + j] * INV_T;
                        int col = ntile * TILE + wn * 32 + nf * 8 + quad * 2 + j;
                        if (v > best || (v == best && col < bc)) { best = v; bc = col; }
                    }
                }
                #pragma unroll
                for (int m = 1; m <= 2; m <<= 1) {
                    float ov = __shfl_xor_sync(~0u, best, m);
                    int oc = __shfl_xor_sync(~0u, bc, m);
                    if (ov > best || (ov == best && oc < bc)) { best = ov; bc = oc; }
                }
                if (quad == 0) {
                    int row = mtile * TILE + wm * 64 + mf * 16 + g + 8 * h;
                    unsigned bits = __float_as_uint(best);
                    unsigned u = (bits & 0x80000000u) ? ~bits : (bits | 0x80000000u);
                    unsigned long long packed =
                        ((unsigned long long)u << 32) |
                        (unsigned long long)(0xFFFFFFFFu - (unsigned)bc);
                    atomicMax(&g_max[row], packed);
                }
            }
        }
    } else {
        // centroid tile (ctile <= ntile): column sums always.
        #pragma unroll
        for (int nf = 0; nf < 4; nf++) {
            #pragma unroll
            for (int j = 0; j < 2; j++) {
                float s = 0.0f;
                #pragma unroll
                for (int mf = 0; mf < 4; mf++) {
                    s += __expf(acc[mf][nf][j] * INV_T);
                    s += __expf(acc[mf][nf][2 + j] * INV_T);
                }
                #pragma unroll
                for (int m = 4; m <= 16; m <<= 1)
                    s += __shfl_xor_sync(~0u, s, m);
                if (g == 0)
                    atomicAdd(&g_S[ntile * TILE + wn * 32 + nf * 8 + quad * 2 + j], s);
            }
        }
        // off-diagonal: row sums stand in for the skipped transposed tile.
        if (ctile < ntile) {
            #pragma unroll
            for (int mf = 0; mf < 4; mf++) {
                #pragma unroll
                for (int h = 0; h < 2; h++) {
                    float s = 0.0f;
                    #pragma unroll
                    for (int nf = 0; nf < 4; nf++) {
                        s += __expf(acc[mf][nf][2 * h + 0] * INV_T);
                        s += __expf(acc[mf][nf][2 * h + 1] * INV_T);
                    }
                    #pragma unroll
                    for (int m = 1; m <= 2; m <<= 1)
                        s += __shfl_xor_sync(~0u, s, m);
                    if (quad == 0)
                        atomicAdd(&g_S[ctile * TILE + wm * 64 + mf * 16 + g + 8 * h], s);
                }
            }
        }
    }
}

// ---------------- final scalar reduction -------------------------------------

__global__ void k_final(const float* __restrict__ w, float* __restrict__ out,
                        int out_size) {
    __shared__ float part[256];
    int t = threadIdx.x;
    float acc = 0.0f;
    for (int b = t; b < B_ROWS; b += 256) {
        unsigned long long p = g_max[b];
        float J = 0.0f;
        if (p != 0ull) {
            unsigned u = (unsigned)(p >> 32);
            int col = (int)(0xFFFFFFFFu - (unsigned)(p & 0xFFFFFFFFull));
            float m = (u & 0x80000000u) ? __uint_as_float(u & 0x7FFFFFFFu)
                                        : __uint_as_float(~u);
            float pep = expf(m) * w[b];
            float Sv  = (col >= 0 && col < K_ROWS) ? g_S[col] : 0.0f;
            J = logf(pep) - logf(pep + Sv);
            if (isnan(J)) J = 0.0f;
        }
        acc += J;
    }
    part[t] = acc;
    __syncthreads();
    #pragma unroll
    for (int o = 128; o; o >>= 1) {
        if (t < o) part[t] += part[t + o];
        __syncthreads();
    }
    if (t == 0) out[0] = -(part[0] / (float)B_ROWS);
    for (int i = 1 + t; i < out_size; i += 256) out[i] = 0.0f;
}

// ---------------- launch ------------------------------------------------------

extern "C" void kernel_launch(void* const* d_in, const int* in_sizes, int n_in,
                              void* d_out, int out_size) {
    // Bind inputs BY SIZE (robust to metadata ordering):
    //   features: 1048576, centroids: 2097152, weight: 4096
    const float* features  = nullptr;
    const float* centroids = nullptr;
    const float* weight    = nullptr;
    for (int i = 0; i < n_in; i++) {
        if (in_sizes[i] == B_ROWS * D_DIM)      features  = (const float*)d_in[i];
        else if (in_sizes[i] == K_ROWS * D_DIM) centroids = (const float*)d_in[i];
        else if (in_sizes[i] == B_ROWS)         weight    = (const float*)d_in[i];
    }
    float* out = (float*)d_out;

    k_init<<<32, 256>>>();
    k_feat<<<(B_ROWS * D_DIM) / 256, 256>>>(features);
    k_norm<<<K_ROWS, 256>>>(centroids);

    dim3 grid(X_ROWS / TILE, K_ROWS / TILE);   // (96, 64); lower triangle exits
    k_gemm<<<grid, 256, SMEM_BYTES>>>();

    k_final<<<1, 256>>>(weight, out, out_size);
}

// round 8
// speedup vs baseline: 1.4121x; 1.0636x over previous
#include <cuda_runtime.h>
#include <cuda_bf16.h>
#include <cstdint>

// ============================================================================
// B=4096 features [B,256], K=8192 centroids [K,256], weight [B]
//   c = normalize(centroids, dim=1)
//   prod = features @ c.T / 0.07   -> per-row max m[b], argmax pos[b]
//   S[k] = sum_j exp((c @ c.T / 0.07)[j,k])
//   pep = exp(m)*w ; J = logf(pep) - logf(pep + S[pos]) ; out = -mean(J)
//
// bf16 mma.sync.m16n8k16 + ldmatrix + cp.async double-buffered; fused GEMM
// X=[features; c] @ c.T, CTA tile 128x128, symmetric c@c.T half skipped.
// R7 -> R8: ldsm/MMA interleave inside each K-chunk (cover ldsm latency with
// MMA issue; stop the [load burst][mma burst] phase alternation). mma asm
// non-volatile so ptxas can schedule. k_init fused into k_feat; k_final 1024t.
// ============================================================================

#define B_ROWS 4096
#define K_ROWS 8192
#define D_DIM  256
#define X_ROWS (B_ROWS + K_ROWS)
#define TILE   128
#define FTILES (B_ROWS / TILE)                    // 32 feature m-tiles
#define INV_T  14.285714285714285714f             // 1/0.07

// smem chunk: 128 rows x 32 cols bf16 (64B) padded to 80B rows (conflict-free)
#define ROW_BYTES  80
#define CHUNK_BYTES (TILE * ROW_BYTES)            // 10240
#define STAGE_BYTES (2 * CHUNK_BYTES)             // 20480
#define SMEM_BYTES  (2 * STAGE_BYTES)             // 40960 (< 48K, no attribute)
#define NCHUNK 8                                  // 8 x 32 = K=256

__device__ __nv_bfloat16 g_X[(size_t)X_ROWS * D_DIM];   // [features; c_normalized]
__device__ float g_S[K_ROWS];
__device__ unsigned long long g_max[B_ROWS];            // packed (ordered-float, ~col)

// ---------------- helpers ----------------------------------------------------

static __device__ __forceinline__ uint32_t smem_u32(const void* p) {
    uint32_t a;
    asm("{ .reg .u64 t; cvta.to.shared.u64 t, %1; cvt.u32.u64 %0, t; }"
        : "=r"(a) : "l"(p));
    return a;
}

static __device__ __forceinline__ void cp16(uint32_t dst, const void* src) {
    asm volatile("cp.async.cg.shared.global [%0], [%1], 16;"
                 :: "r"(dst), "l"(src));
}

static __device__ __forceinline__ void ldsm4(uint32_t& r0, uint32_t& r1,
                                             uint32_t& r2, uint32_t& r3,
                                             uint32_t addr) {
    asm volatile("ldmatrix.sync.aligned.m8n8.x4.shared.b16 {%0,%1,%2,%3}, [%4];"
                 : "=r"(r0), "=r"(r1), "=r"(r2), "=r"(r3) : "r"(addr));
}

// non-volatile: pure register op, let ptxas schedule it freely
static __device__ __forceinline__ void mma16816(float* c, const uint32_t* a,
                                                const uint32_t* b) {
    asm("mma.sync.aligned.m16n8k16.row.col.f32.bf16.bf16.f32 "
        "{%0,%1,%2,%3}, {%4,%5,%6,%7}, {%8,%9}, {%0,%1,%2,%3};"
        : "+f"(c[0]), "+f"(c[1]), "+f"(c[2]), "+f"(c[3])
        : "r"(a[0]), "r"(a[1]), "r"(a[2]), "r"(a[3]), "r"(b[0]), "r"(b[1]));
}

// ---------------- prep kernels ----------------------------------------------

__global__ void k_feat(const float* __restrict__ f) {
    int i = blockIdx.x * blockDim.x + threadIdx.x;   // exactly 4096*256 threads
    g_X[i] = __float2bfloat16(f[i]);
    if (i < K_ROWS) g_S[i] = 0.0f;                   // fused init
    if (i < B_ROWS) g_max[i] = 0ull;
}

__global__ void k_norm(const float* __restrict__ cent) {
    __shared__ float ws[8];
    __shared__ float sc;
    int k = blockIdx.x, t = threadIdx.x;             // 256 threads, one row
    float v = cent[(size_t)k * D_DIM + t];
    float s = v * v;
    #pragma unroll
    for (int o = 16; o; o >>= 1) s += __shfl_xor_sync(~0u, s, o);
    if ((t & 31) == 0) ws[t >> 5] = s;
    __syncthreads();
    if (t == 0) {
        float tot = 0.0f;
        #pragma unroll
        for (int i = 0; i < 8; i++) tot += ws[i];
        sc = 1.0f / fmaxf(sqrtf(tot), 1e-12f);
    }
    __syncthreads();
    g_X[(size_t)(B_ROWS + k) * D_DIM + t] = __float2bfloat16(v * sc);
}

// ---------------- fused GEMM + epilogue --------------------------------------
// grid = (96, 64). 256 threads = 8 warps, warp grid 2(M) x 4(N), warp tile 64x32.

__global__ void __launch_bounds__(256, 2) k_gemm() {
    const int mtile = blockIdx.x, ntile = blockIdx.y;
    const bool is_feat = (mtile < FTILES);
    const int ctile = mtile - FTILES;                // centroid row-tile index
    if (!is_feat && ctile > ntile) return;           // symmetric half: skip

    extern __shared__ char smem[];
    const uint32_t sb = smem_u32(smem);
    const int tid = threadIdx.x;
    const int wid = tid >> 5, lid = tid & 31;
    const int wm = wid >> 2, wn = wid & 3;           // warp coords

    const __nv_bfloat16* gA = g_X + (size_t)mtile * TILE * D_DIM;
    const __nv_bfloat16* gB = g_X + (size_t)(B_ROWS + ntile * TILE) * D_DIM;

    float acc[4][4][4];
    #pragma unroll
    for (int a = 0; a < 4; a++)
        #pragma unroll
        for (int b = 0; b < 4; b++)
            #pragma unroll
            for (int i = 0; i < 4; i++) acc[a][b][i] = 0.0f;

    // per-thread cp coords: 512 x 16B per tile; row = idx/4, colc = idx%4
    const int r0c = tid >> 2, c0c = tid & 3;          // idx = tid
    const int r1c = (tid + 256) >> 2, c1c = tid & 3;  // idx = tid + 256

    // ---- prefetch chunk 0 ----
    {
        uint32_t so0 = sb + (uint32_t)(r0c * ROW_BYTES + c0c * 16);
        uint32_t so1 = sb + (uint32_t)(r1c * ROW_BYTES + c1c * 16);
        cp16(so0, gA + (size_t)r0c * D_DIM + c0c * 8);
        cp16(so0 + CHUNK_BYTES, gB + (size_t)r0c * D_DIM + c0c * 8);
        cp16(so1, gA + (size_t)r1c * D_DIM + c1c * 8);
        cp16(so1 + CHUNK_BYTES, gB + (size_t)r1c * D_DIM + c1c * 8);
    }
    asm volatile("cp.async.commit_group;" ::: "memory");

    // ldmatrix address components (per lane)
    const int arow = lid & 15, asel = lid >> 4;
    const int brow = lid & 7;
    const int bsel = lid >> 3;
    const int bn_off = 8 * (bsel >> 1), bk_off = 8 * (bsel & 1);

    #pragma unroll
    for (int kc = 0; kc < NCHUNK; kc++) {
        asm volatile("cp.async.wait_group 0;" ::: "memory");
        __syncthreads();

        // issue loads for chunk kc+1 into the buffer everyone just finished with
        if (kc < NCHUNK - 1) {
            const int nk = kc + 1;
            const uint32_t stage = (uint32_t)(nk & 1) * STAGE_BYTES;
            uint32_t so0 = sb + stage + (uint32_t)(r0c * ROW_BYTES + c0c * 16);
            uint32_t so1 = sb + stage + (uint32_t)(r1c * ROW_BYTES + c1c * 16);
            cp16(so0, gA + (size_t)r0c * D_DIM + nk * 32 + c0c * 8);
            cp16(so0 + CHUNK_BYTES, gB + (size_t)r0c * D_DIM + nk * 32 + c0c * 8);
            cp16(so1, gA + (size_t)r1c * D_DIM + nk * 32 + c1c * 8);
            cp16(so1 + CHUNK_BYTES, gB + (size_t)r1c * D_DIM + nk * 32 + c1c * 8);
            asm volatile("cp.async.commit_group;" ::: "memory");
        }

        const uint32_t sA = sb + (uint32_t)(kc & 1) * STAGE_BYTES;
        const uint32_t sB = sA + CHUNK_BYTES;

        // ---- interleaved 2-ks chunk body ----
        // frag sets: ks0 = k0 bytes 0, ks1 = k0 16
        uint32_t a0[4][4], b0[4][2], a1[4][4], b1[4][2];

        // ldsm A0 (all mf), B0 (both halves)
        #pragma unroll
        for (int mf = 0; mf < 4; mf++) {
            uint32_t ad = sA + (uint32_t)((wm * 64 + mf * 16 + arow) * ROW_BYTES
                                          + (8 * asel) * 2);
            ldsm4(a0[mf][0], a0[mf][1], a0[mf][2], a0[mf][3], ad);
        }
        #pragma unroll
        for (int half = 0; half < 2; half++) {
            uint32_t bd = sB + (uint32_t)((wn * 32 + half * 16 + bn_off + brow) * ROW_BYTES
                                          + bk_off * 2);
            ldsm4(b0[half * 2][0], b0[half * 2][1],
                  b0[half * 2 + 1][0], b0[half * 2 + 1][1], bd);
        }

        // MMA ks0 mf0, mf1 (covers B0/A0 latency window across warps)
        #pragma unroll
        for (int mf = 0; mf < 2; mf++)
            #pragma unroll
            for (int nf = 0; nf < 4; nf++)
                mma16816(acc[mf][nf], a0[mf], b0[nf]);

        // ldsm B1 — latency covered by mf2 MMAs below
        #pragma unroll
        for (int half = 0; half < 2; half++) {
            uint32_t bd = sB + (uint32_t)((wn * 32 + half * 16 + bn_off + brow) * ROW_BYTES
                                          + (16 + bk_off) * 2);
            ldsm4(b1[half * 2][0], b1[half * 2][1],
                  b1[half * 2 + 1][0], b1[half * 2 + 1][1], bd);
        }

        // MMA ks0 mf2
        #pragma unroll
        for (int nf = 0; nf < 4; nf++)
            mma16816(acc[2][nf], a0[2], b0[nf]);

        // ldsm A1 — latency covered by mf3 MMAs below
        #pragma unroll
        for (int mf = 0; mf < 4; mf++) {
            uint32_t ad = sA + (uint32_t)((wm * 64 + mf * 16 + arow) * ROW_BYTES
                                          + (16 + 8 * asel) * 2);
            ldsm4(a1[mf][0], a1[mf][1], a1[mf][2], a1[mf][3], ad);
        }

        // MMA ks0 mf3
        #pragma unroll
        for (int nf = 0; nf < 4; nf++)
            mma16816(acc[3][nf], a0[3], b0[nf]);

        // MMA ks1 (all)
        #pragma unroll
        for (int mf = 0; mf < 4; mf++)
            #pragma unroll
            for (int nf = 0; nf < 4; nf++)
                mma16816(acc[mf][nf], a1[mf], b1[nf]);
    }

    // ---- epilogue ----
    const int quad = lid & 3, g = lid >> 2;
    if (is_feat) {
        // feature rows: per-row max + argmax
        #pragma unroll
        for (int mf = 0; mf < 4; mf++) {
            #pragma unroll
            for (int h = 0; h < 2; h++) {
                float best = -3.4e38f;
                int bc = 0;
                #pragma unroll
                for (int nf = 0; nf < 4; nf++) {
                    #pragma unroll
                    for (int j = 0; j < 2; j++) {
                        float v = acc[mf][nf][2 * h + j] * INV_T;
                        int col = ntile * TILE + wn * 32 + nf * 8 + quad * 2 + j;
                        if (v > best || (v == best && col < bc)) { best = v; bc = col; }
                    }
                }
                #pragma unroll
                for (int m = 1; m <= 2; m <<= 1) {
                    float ov = __shfl_xor_sync(~0u, best, m);
                    int oc = __shfl_xor_sync(~0u, bc, m);
                    if (ov > best || (ov == best && oc < bc)) { best = ov; bc = oc; }
                }
                if (quad == 0) {
                    int row = mtile * TILE + wm * 64 + mf * 16 + g + 8 * h;
                    unsigned bits = __float_as_uint(best);
                    unsigned u = (bits & 0x80000000u) ? ~bits : (bits | 0x80000000u);
                    unsigned long long packed =
                        ((unsigned long long)u << 32) |
                        (unsigned long long)(0xFFFFFFFFu - (unsigned)bc);
                    atomicMax(&g_max[row], packed);
                }
            }
        }
    } else {
        // centroid tile (ctile <= ntile): column sums always.
        #pragma unroll
        for (int nf = 0; nf < 4; nf++) {
            #pragma unroll
            for (int j = 0; j < 2; j++) {
                float s = 0.0f;
                #pragma unroll
                for (int mf = 0; mf < 4; mf++) {
                    s += __expf(acc[mf][nf][j] * INV_T);
                    s += __expf(acc[mf][nf][2 + j] * INV_T);
                }
                #pragma unroll
                for (int m = 4; m <= 16; m <<= 1)
                    s += __shfl_xor_sync(~0u, s, m);
                if (g == 0)
                    atomicAdd(&g_S[ntile * TILE + wn * 32 + nf * 8 + quad * 2 + j], s);
            }
        }
        // off-diagonal: row sums stand in for the skipped transposed tile.
        if (ctile < ntile) {
            #pragma unroll
            for (int mf = 0; mf < 4; mf++) {
                #pragma unroll
                for (int h = 0; h < 2; h++) {
                    float s = 0.0f;
                    #pragma unroll
                    for (int nf = 0; nf < 4; nf++) {
                        s += __expf(acc[mf][nf][2 * h + 0] * INV_T);
                        s += __expf(acc[mf][nf][2 * h + 1] * INV_T);
                    }
                    #pragma unroll
                    for (int m = 1; m <= 2; m <<= 1)
                        s += __shfl_xor_sync(~0u, s, m);
                    if (quad == 0)
                        atomicAdd(&g_S[ctile * TILE + wm * 64 + mf * 16 + g + 8 * h], s);
                }
            }
        }
    }
}

// ---------------- final scalar reduction -------------------------------------

__global__ void k_final(const float* __restrict__ w, float* __restrict__ out,
                        int out_size) {
    __shared__ float part[1024];
    int t = threadIdx.x;
    float acc = 0.0f;
    for (int b = t; b < B_ROWS; b += 1024) {
        unsigned long long p = g_max[b];
        float J = 0.0f;
        if (p != 0ull) {
            unsigned u = (unsigned)(p >> 32);
            int col = (int)(0xFFFFFFFFu - (unsigned)(p & 0xFFFFFFFFull));
            float m = (u & 0x80000000u) ? __uint_as_float(u & 0x7FFFFFFFu)
                                        : __uint_as_float(~u);
            float pep = expf(m) * w[b];
            float Sv  = (col >= 0 && col < K_ROWS) ? g_S[col] : 0.0f;
            J = logf(pep) - logf(pep + Sv);
            if (isnan(J)) J = 0.0f;
        }
        acc += J;
    }
    part[t] = acc;
    __syncthreads();
    #pragma unroll
    for (int o = 512; o; o >>= 1) {
        if (t < o) part[t] += part[t + o];
        __syncthreads();
    }
    if (t == 0) out[0] = -(part[0] / (float)B_ROWS);
    for (int i = 1 + t; i < out_size; i += 1024) out[i] = 0.0f;
}

// ---------------- launch ------------------------------------------------------

extern "C" void kernel_launch(void* const* d_in, const int* in_sizes, int n_in,
                              void* d_out, int out_size) {
    // Bind inputs BY SIZE (robust to metadata ordering):
    //   features: 1048576, centroids: 2097152, weight: 4096
    const float* features  = nullptr;
    const float* centroids = nullptr;
    const float* weight    = nullptr;
    for (int i = 0; i < n_in; i++) {
        if (in_sizes[i] == B_ROWS * D_DIM)      features  = (const float*)d_in[i];
        else if (in_sizes[i] == K_ROWS * D_DIM) centroids = (const float*)d_in[i];
        else if (in_sizes[i] == B_ROWS)         weight    = (const float*)d_in[i];
    }
    float* out = (float*)d_out;

    k_feat<<<(B_ROWS * D_DIM) / 256, 256>>>(features);   // also zeroes g_S/g_max
    k_norm<<<K_ROWS, 256>>>(centroids);

    dim3 grid(X_ROWS / TILE, K_ROWS / TILE);   // (96, 64); lower triangle exits
    k_gemm<<<grid, 256, SMEM_BYTES>>>();

    k_final<<<1, 1024>>>(weight, out, out_size);
}